// round 11
// baseline (speedup 1.0000x reference)
#include <cuda_runtime.h>

// Problem constants
#define N_TOK    16384          // 4 * 16*16*16 tokens
#define N_E      8192           // codebook size
#define E_DIM    256            // code dim
#define OUT_ELEMS 4194304       // 4*256*16*16*16
#define LOSS_OFF  OUT_ELEMS
#define PERP_OFF  (OUT_ELEMS + 1)
#define IDX_OFF   (OUT_ELEMS + 2)

// Scratch (static device globals — allowed by harness rules)
__device__ float g_wT[E_DIM * N_E];   // weight transposed: [k][n]
__device__ float g_wn[N_E];           // |w_n|^2
__device__ int   g_idx[N_TOK];
__device__ int   g_counts[N_E];
__device__ float g_partial[256];

typedef unsigned long long u64;

__device__ __forceinline__ u64 pk2(float lo, float hi) {
    u64 r;
    asm("mov.b64 %0, {%1, %2};" : "=l"(r) : "f"(lo), "f"(hi));
    return r;
}
__device__ __forceinline__ void upk2(u64 v, float& lo, float& hi) {
    asm("mov.b64 {%0, %1}, %2;" : "=f"(lo), "=f"(hi) : "l"(v));
}
// packed fp32x2 FMA: d = a*b + d (two exact fp32 FMAs per instruction)
__device__ __forceinline__ void fma2(u64& d, u64 a, u64 b) {
    asm("fma.rn.f32x2 %0, %1, %2, %0;" : "+l"(d) : "l"(a), "l"(b));
}

// ---------------------------------------------------------------------------
// Zero the histogram
__global__ void zero_kernel() {
    int i = blockIdx.x * blockDim.x + threadIdx.x;
    if (i < N_E) g_counts[i] = 0;
}

// ---------------------------------------------------------------------------
// Transpose weight [N_E, E_DIM] -> g_wT [E_DIM, N_E]
__global__ void transpose_kernel(const float* __restrict__ w) {
    __shared__ float tile[32][33];
    int bx = blockIdx.x;            // k tile (0..7)
    int by = blockIdx.y;            // n tile (0..255)
    int tx = threadIdx.x;           // 0..31
    int ty = threadIdx.y;           // 0..7
#pragma unroll
    for (int j = 0; j < 32; j += 8)
        tile[ty + j][tx] = w[(by * 32 + ty + j) * E_DIM + bx * 32 + tx];
    __syncthreads();
#pragma unroll
    for (int j = 0; j < 32; j += 8)
        g_wT[(bx * 32 + ty + j) * N_E + by * 32 + tx] = tile[tx][ty + j];
}

// ---------------------------------------------------------------------------
// wn[j] = sum_k wT[k][j]^2  (coalesced along j)
__global__ void wn_kernel() {
    int j = blockIdx.x * 256 + threadIdx.x;
    float s = 0.f;
#pragma unroll 8
    for (int k = 0; k < E_DIM; k++) {
        float v = g_wT[k * N_E + j];
        s = fmaf(v, v, s);
    }
    g_wn[j] = s;
}

// ---------------------------------------------------------------------------
// Argmin kernel: tiled 128x128x32 fp32 GEMM with distance epilogue.
// score(t, n) = |w_n|^2 - 2 * z_t . w_n   (|z_t|^2 constant per token)
#define BM 128
#define BN 128
#define BK 32

__global__ __launch_bounds__(256) void argmin_kernel(const float* __restrict__ z) {
    __shared__ float zs[BK][BM];
    __shared__ float ws[BK][BN];

    const int tid = threadIdx.x;
    const int tx = tid & 15;        // code group (16)
    const int ty = tid >> 4;        // token group (16)
    const int t0 = blockIdx.x * BM; // 128 tokens, all in same batch (4096 % 128 == 0)
    const int b  = t0 >> 12;
    const int s0 = t0 & 4095;
    const float* zbase = z + (size_t)b * 1048576 + s0;  // zf[t][c] = z[b, c, s]

    float best[8];
    int   bidx[8];
#pragma unroll
    for (int i = 0; i < 8; i++) { best[i] = 1e30f; bidx[i] = 0; }

    for (int nt = 0; nt < N_E / BN; nt++) {
        const int n0 = nt * BN;

        u64 acc[8][4];
#pragma unroll
        for (int i = 0; i < 8; i++)
#pragma unroll
            for (int p = 0; p < 4; p++) acc[i][p] = 0ull;

        for (int kt = 0; kt < E_DIM / BK; kt++) {
            const int k0 = kt * BK;
            // load z tile: zs[k][m] = z[b, k0+k, s0+m]  (coalesced float4)
#pragma unroll
            for (int it = 0; it < 4; it++) {
                int slot = it * 256 + tid;
                int k = slot >> 5;
                int m4 = (slot & 31) << 2;
                *(float4*)&zs[k][m4] =
                    *(const float4*)&zbase[(size_t)(k0 + k) * 4096 + m4];
            }
            // load w tile from transposed weights (coalesced float4)
#pragma unroll
            for (int it = 0; it < 4; it++) {
                int slot = it * 256 + tid;
                int k = slot >> 5;
                int n4 = (slot & 31) << 2;
                *(float4*)&ws[k][n4] =
                    *(const float4*)&g_wT[(size_t)(k0 + k) * N_E + n0 + n4];
            }
            __syncthreads();

#pragma unroll 8
            for (int k = 0; k < BK; k++) {
                float4 za = *(const float4*)&zs[k][ty * 8];
                float4 zb = *(const float4*)&zs[k][ty * 8 + 4];
                float4 wa = *(const float4*)&ws[k][tx * 8];
                float4 wb = *(const float4*)&ws[k][tx * 8 + 4];
                u64 wp[4];
                wp[0] = pk2(wa.x, wa.y);
                wp[1] = pk2(wa.z, wa.w);
                wp[2] = pk2(wb.x, wb.y);
                wp[3] = pk2(wb.z, wb.w);
                float zv[8] = {za.x, za.y, za.z, za.w, zb.x, zb.y, zb.z, zb.w};
#pragma unroll
                for (int i = 0; i < 8; i++) {
                    u64 zz = pk2(zv[i], zv[i]);
#pragma unroll
                    for (int p = 0; p < 4; p++) fma2(acc[i][p], zz, wp[p]);
                }
            }
            __syncthreads();
        }

        // epilogue: score = wn - 2*dot, keep running min (ties -> lowest n wins)
        float wn8[8];
#pragma unroll
        for (int j = 0; j < 8; j++) wn8[j] = g_wn[n0 + tx * 8 + j];
#pragma unroll
        for (int i = 0; i < 8; i++) {
#pragma unroll
            for (int p = 0; p < 4; p++) {
                float d0, d1;
                upk2(acc[i][p], d0, d1);
                float sc0 = fmaf(-2.f, d0, wn8[2 * p]);
                float sc1 = fmaf(-2.f, d1, wn8[2 * p + 1]);
                int nA = n0 + tx * 8 + 2 * p;
                if (sc0 < best[i]) { best[i] = sc0; bidx[i] = nA; }
                if (sc1 < best[i]) { best[i] = sc1; bidx[i] = nA + 1; }
            }
        }
    }

    // reduce across the 16 tx lanes (lanes [0..15] / [16..31] within each warp)
#pragma unroll
    for (int i = 0; i < 8; i++) {
        float v = best[i];
        int   bi = bidx[i];
#pragma unroll
        for (int off = 8; off >= 1; off >>= 1) {
            float ov = __shfl_xor_sync(0xffffffffu, v, off);
            int   oi = __shfl_xor_sync(0xffffffffu, bi, off);
            if (ov < v || (ov == v && oi < bi)) { v = ov; bi = oi; }
        }
        if (tx == 0) {
            int t = t0 + ty * 8 + i;
            g_idx[t] = bi;
            atomicAdd(&g_counts[bi], 1);
        }
    }
}

// ---------------------------------------------------------------------------
// Gather + straight-through output + deterministic loss partials.
// out[b,c,s] = z_t + (z_q - z_t); loss partial = sum (z_q - z_t)^2
__global__ __launch_bounds__(256) void gather_kernel(const float* __restrict__ z,
                                                     float* __restrict__ out,
                                                     int out_size) {
    __shared__ float red[256];
    const int blk = blockIdx.x;
    const int t0 = blk * 64;            // 64 tokens per block (same batch)
    const int b  = t0 >> 12;
    const int s0 = t0 & 4095;
    const int tid = threadIdx.x;
    const int i  = tid & 63;            // token within group
    const int cg = tid >> 6;            // channel group (0..3)
    const int t  = t0 + i;
    const int j  = g_idx[t];
    const size_t base = (size_t)b * 1048576 + s0 + i;

    float lsum = 0.f;
#pragma unroll 4
    for (int cc = 0; cc < 64; cc++) {
        int c = cg * 64 + cc;
        float zt = z[base + (size_t)c * 4096];
        float zq = g_wT[(size_t)c * N_E + j];
        float d = zq - zt;
        out[base + (size_t)c * 4096] = zt + d;   // straight-through value
        lsum = fmaf(d, d, lsum);
    }

    red[tid] = lsum;
    __syncthreads();
    for (int s = 128; s >= 1; s >>= 1) {
        if (tid < s) red[tid] += red[tid + s];
        __syncthreads();
    }
    if (tid == 0) g_partial[blk] = red[0];

    if (cg == 0 && out_size >= IDX_OFF + N_TOK)
        out[IDX_OFF + t] = (float)j;
}

// ---------------------------------------------------------------------------
// Final: loss + perplexity (deterministic fixed-order reductions)
__global__ void final_kernel(float* __restrict__ out, int out_size) {
    __shared__ float red[256];
    const int tid = threadIdx.x;

    // loss = BETA * mean((zq - zt)^2)
    red[tid] = g_partial[tid];
    __syncthreads();
    for (int s = 128; s >= 1; s >>= 1) {
        if (tid < s) red[tid] += red[tid + s];
        __syncthreads();
    }
    float loss = 0.25f * red[0] / (float)OUT_ELEMS;
    __syncthreads();

    // perplexity = exp(-sum p log(p + 1e-10))
    float h = 0.f;
#pragma unroll
    for (int k = 0; k < N_E / 256; k++) {
        float p = (float)g_counts[k * 256 + tid] * (1.f / (float)N_TOK);
        h += p * logf(p + 1e-10f);
    }
    red[tid] = h;
    __syncthreads();
    for (int s = 128; s >= 1; s >>= 1) {
        if (tid < s) red[tid] += red[tid + s];
        __syncthreads();
    }
    if (tid == 0) {
        if (out_size > LOSS_OFF) out[LOSS_OFF] = loss;
        if (out_size > PERP_OFF) out[PERP_OFF] = expf(-red[0]);
    }
}

// ---------------------------------------------------------------------------
extern "C" void kernel_launch(void* const* d_in, const int* in_sizes, int n_in,
                              void* d_out, int out_size) {
    const float* z = (const float*)d_in[0];
    const float* w = (const float*)d_in[1];
    // defensive: inputs are (z: 4194304, weight: 2097152) — swap if reversed
    if (n_in >= 2 && in_sizes[0] == N_E * E_DIM && in_sizes[1] == OUT_ELEMS) {
        const float* tmp = z; z = w; w = tmp;
    }
    float* out = (float*)d_out;

    zero_kernel<<<32, 256>>>();
    transpose_kernel<<<dim3(8, 256), dim3(32, 8)>>>(w);
    wn_kernel<<<N_E / 256, 256>>>();
    argmin_kernel<<<N_TOK / BM, 256>>>(z);
    gather_kernel<<<N_TOK / 64, 256>>>(z, out, out_size);
    final_kernel<<<1, 256>>>(out, out_size);
}